// round 7
// baseline (speedup 1.0000x reference)
#include <cuda_runtime.h>
#include <float.h>

#define NN   100000
#define IND  128
#define HIDD 256
#define NG   256

// ---------------- static device scratch (allocation-free rule) ----------------
__device__ float g_m[NN * IND];        // relu(x @ W_pool + b_pool)
__device__ float g_neigh[NN * IND];    // segment_max over in-edges
__device__ float g_h1[NN * HIDD];
__device__ float g_h2[NN * HIDD];
__device__ float g_h3[NN * HIDD];
__device__ float g_final[NG * HIDD];   // 1/zsum per (graph, feature)
__device__ int   g_start[NG + 1];      // node range per graph (graph_id sorted)

// ---------------- packed f32x2 FMA (FFMA2, sm_100+) ----------------
__device__ __forceinline__ void fma2(unsigned long long& d,
                                     unsigned long long a,
                                     unsigned long long b) {
    asm("fma.rn.f32x2 %0, %1, %2, %0;" : "+l"(d) : "l"(a), "l"(b));
}
__device__ __forceinline__ unsigned long long pk_dup(float v) {
    unsigned long long d;
    asm("mov.b64 %0, {%1, %1};" : "=l"(d) : "f"(v));
    return d;
}

// ---------------- small utility kernels ----------------
__global__ void zero_neigh_kernel(int n4) {
    int i = blockIdx.x * blockDim.x + threadIdx.x;
    if (i < n4) reinterpret_cast<float4*>(g_neigh)[i] = make_float4(0.f, 0.f, 0.f, 0.f);
}

// graph_id is sorted: start[g] = lower_bound(gid, g). One thread per g (0..G).
__global__ void find_starts_kernel(const int* __restrict__ gid, int n, int G) {
    int g = blockIdx.x * blockDim.x + threadIdx.x;
    if (g > G) return;
    int lo = 0, hi = n;
    while (lo < hi) {
        int mid = (lo + hi) >> 1;
        if (gid[mid] < g) lo = mid + 1; else hi = mid;
    }
    g_start[g] = lo;
}

// ---------------- fused (dual-A) GEMM + bias + relu, FFMA2 inner loop --------
// C[M,N] = relu(A1[M,K1] @ B1[K1,N] + A2[M,K2] @ B2[K2,N] + bias)
// 128x128 block tile, BK=8, 256 threads, 8x8 per-thread microtile.
// Accumulators packed along rows (f32x2); B stored DUPLICATED {v,v} in smem so
// both FFMA2 operands come straight from 64-bit shared loads (zero pack ops).
template<int K1, int K2, int N>
__global__ __launch_bounds__(256, 2)
void gemm_bias_relu(const float* __restrict__ A1, const float* __restrict__ A2,
                    const float* __restrict__ B1, const float* __restrict__ B2,
                    const float* __restrict__ bias, float* __restrict__ C, int M)
{
    constexpr int KT = K1 + K2;
    constexpr int T  = KT / 8;

    __shared__ float              As[8][132];   // transposed A tile, padded
    __shared__ unsigned long long Bs[8][128];   // duplicated {v,v} per column

    const int tid     = threadIdx.x;
    const int rowbase = blockIdx.x * 128;
    const int colbase = blockIdx.y * 128;

    const int a_row  = tid >> 1;          // 0..127
    const int a_k0   = (tid & 1) * 4;     // 0 or 4
    const int a_grow = rowbase + a_row;
    const int b_krow = tid >> 5;          // 0..7
    const int b_q    = (tid & 31) * 4;    // 0..124

    const int tx = tid & 15;              // col group base: tx*4 and 64+tx*4
    const int ty = tid >> 4;              // row base: ty*8

    // accp[ip][j]: rows {2ip, 2ip+1}, logical col j (j<4 -> group0, j>=4 -> group1)
    unsigned long long accp[4][8];
#pragma unroll
    for (int ip = 0; ip < 4; ++ip)
#pragma unroll
        for (int j = 0; j < 8; ++j) accp[ip][j] = 0ull;

    float4 pa, pb;

    auto fetchA = [&](int t) {
        int kk = t * 8 + a_k0;
        if (a_grow >= M) { pa = make_float4(0.f, 0.f, 0.f, 0.f); return; }
        const float* p;
        if constexpr (K2 == 0) {
            p = A1 + a_grow * K1 + kk;
        } else {
            p = (kk < K1) ? (A1 + a_grow * K1 + kk)
                          : (A2 + a_grow * K2 + (kk - K1));
        }
        pa = *reinterpret_cast<const float4*>(p);
    };
    auto fetchB = [&](int t) {
        int kg = t * 8 + b_krow;
        const float* p;
        if constexpr (K2 == 0) {
            p = B1 + kg * N + colbase + b_q;
        } else {
            p = (kg < K1) ? (B1 + kg * N + colbase + b_q)
                          : (B2 + (kg - K1) * N + colbase + b_q);
        }
        pb = *reinterpret_cast<const float4*>(p);
    };

    fetchA(0);
    fetchB(0);

#pragma unroll 1
    for (int t = 0; t < T; ++t) {
        As[a_k0 + 0][a_row] = pa.x;
        As[a_k0 + 1][a_row] = pa.y;
        As[a_k0 + 2][a_row] = pa.z;
        As[a_k0 + 3][a_row] = pa.w;
        Bs[b_krow][b_q + 0] = pk_dup(pb.x);
        Bs[b_krow][b_q + 1] = pk_dup(pb.y);
        Bs[b_krow][b_q + 2] = pk_dup(pb.z);
        Bs[b_krow][b_q + 3] = pk_dup(pb.w);
        __syncthreads();

        if (t + 1 < T) { fetchA(t + 1); fetchB(t + 1); }

#pragma unroll
        for (int k = 0; k < 8; ++k) {
            // A row-pairs: 4 x 64-bit loads (2 x LDS.128), heavily broadcast
            ulonglong2 aA = *reinterpret_cast<const ulonglong2*>(&As[k][ty * 8]);
            ulonglong2 aB = *reinterpret_cast<const ulonglong2*>(&As[k][ty * 8 + 4]);
            unsigned long long a2[4] = {aA.x, aA.y, aB.x, aB.y};
#pragma unroll
            for (int g = 0; g < 2; ++g) {
                const unsigned long long* bp = &Bs[k][g * 64 + tx * 4];
                ulonglong2 b01 = *reinterpret_cast<const ulonglong2*>(bp);
                ulonglong2 b23 = *reinterpret_cast<const ulonglong2*>(bp + 2);
                unsigned long long b2[4] = {b01.x, b01.y, b23.x, b23.y};
#pragma unroll
                for (int ip = 0; ip < 4; ++ip)
#pragma unroll
                    for (int jj = 0; jj < 4; ++jj)
                        fma2(accp[ip][g * 4 + jj], a2[ip], b2[jj]);
            }
        }
        __syncthreads();
    }

    float bia[8];
#pragma unroll
    for (int g = 0; g < 2; ++g)
#pragma unroll
        for (int jj = 0; jj < 4; ++jj)
            bia[g * 4 + jj] = bias[colbase + g * 64 + tx * 4 + jj];

#pragma unroll
    for (int ip = 0; ip < 4; ++ip) {
        float2 c[8];
#pragma unroll
        for (int j = 0; j < 8; ++j)
            c[j] = *reinterpret_cast<float2*>(&accp[ip][j]);
        int r0 = rowbase + ty * 8 + 2 * ip;
#pragma unroll
        for (int half = 0; half < 2; ++half) {
            int r = r0 + half;
            if (r < M) {
#pragma unroll
                for (int g = 0; g < 2; ++g) {
                    float4 o;
                    o.x = fmaxf((half ? c[g*4+0].y : c[g*4+0].x) + bia[g*4+0], 0.f);
                    o.y = fmaxf((half ? c[g*4+1].y : c[g*4+1].x) + bia[g*4+1], 0.f);
                    o.z = fmaxf((half ? c[g*4+2].y : c[g*4+2].x) + bia[g*4+2], 0.f);
                    o.w = fmaxf((half ? c[g*4+3].y : c[g*4+3].x) + bia[g*4+3], 0.f);
                    *reinterpret_cast<float4*>(&C[r * N + colbase + g * 64 + tx * 4]) = o;
                }
            }
        }
    }
}

// ---------------- edge segment_max (relu output >= 0 -> int atomicMax trick) ----
// warp per edge, lane handles 4 features; pre-read current max, atomic only
// on record-breaking values (monotone, race-safe).
__global__ void edge_max_kernel(const int* __restrict__ src, const int* __restrict__ dst,
                                int n_edges)
{
    int gt = blockIdx.x * blockDim.x + threadIdx.x;
    int e  = gt >> 5;
    if (e >= n_edges) return;
    int c = (gt & 31) * 4;
    int s = __ldg(&src[e]);
    int d = __ldg(&dst[e]);
    float4 v   = *reinterpret_cast<const float4*>(&g_m[s * IND + c]);
    float* nrow = &g_neigh[d * IND + c];
    float4 cur = *reinterpret_cast<const float4*>(nrow);
    int*   ni  = reinterpret_cast<int*>(nrow);
    if (v.x > cur.x) atomicMax(ni + 0, __float_as_int(v.x));
    if (v.y > cur.y) atomicMax(ni + 1, __float_as_int(v.y));
    if (v.z > cur.z) atomicMax(ni + 2, __float_as_int(v.z));
    if (v.w > cur.w) atomicMax(ni + 3, __float_as_int(v.w));
}

// ---------------- per-graph online softmax denominator ----------------
// final[g,f] = max_nodes(exp(h-gmax)/zsum) = 1/zsum (exp monotone, gmax = max h)
__global__ void softmax_final_kernel()
{
    int g = blockIdx.x;
    int f = threadIdx.x;
    int s = g_start[g], e = g_start[g + 1];
    const float* __restrict__ h = g_h3;

    float mx0 = -FLT_MAX, mx1 = -FLT_MAX, mx2 = -FLT_MAX, mx3 = -FLT_MAX;
    float s0 = 0.f, s1 = 0.f, s2 = 0.f, s3 = 0.f;

    int i = s;
    for (; i + 4 <= e; i += 4) {
        float v0 = h[(i + 0) * HIDD + f];
        float v1 = h[(i + 1) * HIDD + f];
        float v2 = h[(i + 2) * HIDD + f];
        float v3 = h[(i + 3) * HIDD + f];
        if (v0 > mx0) { s0 *= __expf(mx0 - v0); mx0 = v0; }
        s0 += __expf(v0 - mx0);
        if (v1 > mx1) { s1 *= __expf(mx1 - v1); mx1 = v1; }
        s1 += __expf(v1 - mx1);
        if (v2 > mx2) { s2 *= __expf(mx2 - v2); mx2 = v2; }
        s2 += __expf(v2 - mx2);
        if (v3 > mx3) { s3 *= __expf(mx3 - v3); mx3 = v3; }
        s3 += __expf(v3 - mx3);
    }
    for (; i < e; ++i) {
        float v = h[i * HIDD + f];
        if (v > mx0) { s0 *= __expf(mx0 - v); mx0 = v; }
        s0 += __expf(v - mx0);
    }

    float Mx = fmaxf(fmaxf(mx0, mx1), fmaxf(mx2, mx3));
    float S  = s0 * __expf(mx0 - Mx) + s1 * __expf(mx1 - Mx)
             + s2 * __expf(mx2 - Mx) + s3 * __expf(mx3 - Mx);
    g_final[g * HIDD + f] = (e > s) ? (1.0f / S) : 0.f;
}

// ---------------- tiny readout: out = final @ Wr + br ----------------
__global__ void readout_kernel(const float* __restrict__ Wr, const float* __restrict__ br,
                               float* __restrict__ out, int ngr)
{
    int t = blockIdx.x * blockDim.x + threadIdx.x;
    if (t < ngr * 2) {
        int g = t >> 1, o = t & 1;
        float acc = br[o];
        const float* fr = &g_final[g * HIDD];
#pragma unroll 8
        for (int f = 0; f < HIDD; ++f) acc = fmaf(fr[f], Wr[f * 2 + o], acc);
        out[t] = acc;
    }
}

// ---------------- launch ----------------
extern "C" void kernel_launch(void* const* d_in, const int* in_sizes, int n_in,
                              void* d_out, int out_size)
{
    const float* x       = (const float*)d_in[0];
    const float* W_pool  = (const float*)d_in[1];
    const float* b_pool  = (const float*)d_in[2];
    const float* W_self  = (const float*)d_in[3];
    const float* W_neigh = (const float*)d_in[4];
    const float* b_sage  = (const float*)d_in[5];
    const float* W1      = (const float*)d_in[6];
    const float* b1      = (const float*)d_in[7];
    const float* W2      = (const float*)d_in[8];
    const float* b2      = (const float*)d_in[9];
    const float* Wr      = (const float*)d_in[10];
    const float* br      = (const float*)d_in[11];
    const int*   src     = (const int*)d_in[12];
    const int*   dst     = (const int*)d_in[13];
    const int*   gid     = (const int*)d_in[14];
    float*       out     = (float*)d_out;

    const int M = in_sizes[0] / IND;   // 100000
    const int E = in_sizes[12];        // 1600000
    const int G = out_size / 2;        // 256

    void *pm, *pn, *ph1, *ph2, *ph3;
    cudaGetSymbolAddress(&pm,  g_m);
    cudaGetSymbolAddress(&pn,  g_neigh);
    cudaGetSymbolAddress(&ph1, g_h1);
    cudaGetSymbolAddress(&ph2, g_h2);
    cudaGetSymbolAddress(&ph3, g_h3);

    // stage 0: neigh zero-init + graph ranges (binary search over sorted gid)
    const int n4 = (M * IND) / 4;
    zero_neigh_kernel<<<(n4 + 255) / 256, 256>>>(n4);
    find_starts_kernel<<<1, 512>>>(gid, M, G);

    const int MB = (M + 127) / 128;

    // stage 1: m = relu(x @ W_pool + b_pool)
    gemm_bias_relu<128, 0, 128><<<dim3(MB, 1), 256>>>(
        x, nullptr, W_pool, nullptr, b_pool, (float*)pm, M);

    // stage 2: neigh = segment_max(m[src], dst)
    long ethreads = (long)E * 32;
    edge_max_kernel<<<(unsigned)((ethreads + 255) / 256), 256>>>(src, dst, E);

    // stage 3: h1 = relu(x @ W_self + neigh @ W_neigh + b_sage)   (fused K=256)
    gemm_bias_relu<128, 128, 256><<<dim3(MB, 2), 256>>>(
        x, (const float*)pn, W_self, W_neigh, b_sage, (float*)ph1, M);

    // stage 4/5: MLP
    gemm_bias_relu<256, 0, 256><<<dim3(MB, 2), 256>>>(
        (const float*)ph1, nullptr, W1, nullptr, b1, (float*)ph2, M);
    gemm_bias_relu<256, 0, 256><<<dim3(MB, 2), 256>>>(
        (const float*)ph2, nullptr, W2, nullptr, b2, (float*)ph3, M);

    // stage 6: per-graph softmax denominator -> final = 1/zsum
    softmax_final_kernel<<<G, HIDD>>>();

    // stage 7: out = final @ Wr + br
    readout_kernel<<<(G * 2 + 255) / 256, 256>>>(Wr, br, out, G);
}

// round 8
// speedup vs baseline: 1.7295x; 1.7295x over previous
#include <cuda_runtime.h>
#include <float.h>

#define NN   100000
#define NE   1600000
#define IND  128
#define HIDD 256
#define NG   256

// ---------------- static device scratch (allocation-free rule) ----------------
__device__ float g_m[NN * IND];        // relu(x @ W_pool + b_pool)
__device__ float g_neigh[NN * IND];    // segment_max over in-edges
__device__ float g_h1[NN * HIDD];
__device__ float g_h2[NN * HIDD];
__device__ float g_h3[NN * HIDD];
__device__ float g_final[NG * HIDD];   // 1/zsum per (graph, feature)
__device__ int   g_start[NG + 1];      // node range per graph (graph_id sorted)

// CSR scratch
__device__ int g_deg[NN];
__device__ int g_cursor[NN];
__device__ int g_off[NN + 1];
__device__ int g_esrc[NE];
__device__ int g_bsum[128];            // per-1024-block sums (98 used)

// ---------------- graph ranges: gid sorted -> binary search ----------------
__global__ void find_starts_kernel(const int* __restrict__ gid, int n, int G) {
    int g = blockIdx.x * blockDim.x + threadIdx.x;
    if (g > G) return;
    int lo = 0, hi = n;
    while (lo < hi) {
        int mid = (lo + hi) >> 1;
        if (gid[mid] < g) lo = mid + 1; else hi = mid;
    }
    g_start[g] = lo;
}

// ---------------- CSR build ----------------
__global__ void zero_deg_kernel(int n) {
    int i = blockIdx.x * blockDim.x + threadIdx.x;
    if (i < n) g_deg[i] = 0;
}
__global__ void hist_kernel(const int* __restrict__ dst, int ne) {
    int e = blockIdx.x * blockDim.x + threadIdx.x;
    if (e < ne) atomicAdd(&g_deg[dst[e]], 1);
}
// per-1024-chunk sums
__global__ void block_sums_kernel(int n) {
    __shared__ int sh[1024];
    int i = blockIdx.x * 1024 + threadIdx.x;
    sh[threadIdx.x] = (i < n) ? g_deg[i] : 0;
    __syncthreads();
    for (int s = 512; s > 0; s >>= 1) {
        if (threadIdx.x < s) sh[threadIdx.x] += sh[threadIdx.x + s];
        __syncthreads();
    }
    if (threadIdx.x == 0) g_bsum[blockIdx.x] = sh[0];
}
// exclusive scan of block sums (single block), also writes g_off[NN]
__global__ void scan_bsum_kernel(int nb, int n, int ne) {
    __shared__ int sh[128];
    int t = threadIdx.x;
    sh[t] = (t < nb) ? g_bsum[t] : 0;
    __syncthreads();
    // Hillis-Steele inclusive
    for (int d = 1; d < 128; d <<= 1) {
        int v = (t >= d) ? sh[t - d] : 0;
        __syncthreads();
        sh[t] += v;
        __syncthreads();
    }
    if (t < nb) g_bsum[t] = (t == 0) ? 0 : sh[t - 1];   // exclusive
    if (t == 0) g_off[n] = ne;
}
// per-chunk exclusive scan + chunk offset -> g_off, g_cursor
__global__ void scan_block_kernel(int n) {
    __shared__ int sh[1024];
    int t = threadIdx.x;
    int i = blockIdx.x * 1024 + t;
    int v = (i < n) ? g_deg[i] : 0;
    sh[t] = v;
    __syncthreads();
    for (int d = 1; d < 1024; d <<= 1) {
        int u = (t >= d) ? sh[t - d] : 0;
        __syncthreads();
        sh[t] += u;
        __syncthreads();
    }
    if (i < n) {
        int off = g_bsum[blockIdx.x] + sh[t] - v;   // exclusive
        g_off[i] = off;
        g_cursor[i] = off;
    }
}
__global__ void scatter_kernel(const int* __restrict__ src, const int* __restrict__ dst, int ne) {
    int e = blockIdx.x * blockDim.x + threadIdx.x;
    if (e < ne) {
        int pos = atomicAdd(&g_cursor[dst[e]], 1);
        g_esrc[pos] = src[e];
    }
}

// ---------------- gather max: warp per dst node, no atomics ----------------
__global__ void gather_max_kernel(int n) {
    int warp = (blockIdx.x * blockDim.x + threadIdx.x) >> 5;
    if (warp >= n) return;
    int lane = threadIdx.x & 31;
    int c = lane * 4;
    int beg = g_off[warp], end = g_off[warp + 1];
    float4 acc = make_float4(0.f, 0.f, 0.f, 0.f);
    int j = beg;
    for (; j + 2 <= end; j += 2) {
        int s0 = __ldg(&g_esrc[j]);
        int s1 = __ldg(&g_esrc[j + 1]);
        float4 v0 = *reinterpret_cast<const float4*>(&g_m[s0 * IND + c]);
        float4 v1 = *reinterpret_cast<const float4*>(&g_m[s1 * IND + c]);
        acc.x = fmaxf(acc.x, fmaxf(v0.x, v1.x));
        acc.y = fmaxf(acc.y, fmaxf(v0.y, v1.y));
        acc.z = fmaxf(acc.z, fmaxf(v0.z, v1.z));
        acc.w = fmaxf(acc.w, fmaxf(v0.w, v1.w));
    }
    if (j < end) {
        int s0 = __ldg(&g_esrc[j]);
        float4 v0 = *reinterpret_cast<const float4*>(&g_m[s0 * IND + c]);
        acc.x = fmaxf(acc.x, v0.x);
        acc.y = fmaxf(acc.y, v0.y);
        acc.z = fmaxf(acc.z, v0.z);
        acc.w = fmaxf(acc.w, v0.w);
    }
    // relu(m) >= 0 and isolated nodes -> 0 matches reference zero-init
    *reinterpret_cast<float4*>(&g_neigh[warp * IND + c]) = acc;
}

// ---------------- fused (dual-A) GEMM + bias + relu (R6 known-good) ---------
// C[M,N] = relu(A1[M,K1] @ B1[K1,N] + A2[M,K2] @ B2[K2,N] + bias)
// 128x128 block tile, BK=8, 256 threads, 8x8 per-thread microtile,
// register double-buffered global->smem staging.
template<int K1, int K2, int N>
__global__ __launch_bounds__(256, 2)
void gemm_bias_relu(const float* __restrict__ A1, const float* __restrict__ A2,
                    const float* __restrict__ B1, const float* __restrict__ B2,
                    const float* __restrict__ bias, float* __restrict__ C, int M)
{
    constexpr int KT = K1 + K2;
    constexpr int T  = KT / 8;

    __shared__ float As[8][132];   // transposed A tile, padded (conflict-free)
    __shared__ float Bs[8][128];

    const int tid     = threadIdx.x;
    const int rowbase = blockIdx.x * 128;
    const int colbase = blockIdx.y * 128;

    const int a_row  = tid >> 1;          // 0..127
    const int a_k0   = (tid & 1) * 4;     // 0 or 4
    const int a_grow = rowbase + a_row;
    const int b_krow = tid >> 5;          // 0..7
    const int b_q    = (tid & 31) * 4;    // 0..124

    const int tx = tid & 15;
    const int ty = tid >> 4;

    float acc[8][8];
#pragma unroll
    for (int i = 0; i < 8; ++i)
#pragma unroll
        for (int j = 0; j < 8; ++j) acc[i][j] = 0.f;

    float4 pa, pb;

    auto fetchA = [&](int t) {
        int kk = t * 8 + a_k0;
        if (a_grow >= M) { pa = make_float4(0.f, 0.f, 0.f, 0.f); return; }
        const float* p;
        if constexpr (K2 == 0) {
            p = A1 + a_grow * K1 + kk;
        } else {
            p = (kk < K1) ? (A1 + a_grow * K1 + kk)
                          : (A2 + a_grow * K2 + (kk - K1));
        }
        pa = *reinterpret_cast<const float4*>(p);
    };
    auto fetchB = [&](int t) {
        int kg = t * 8 + b_krow;
        const float* p;
        if constexpr (K2 == 0) {
            p = B1 + kg * N + colbase + b_q;
        } else {
            p = (kg < K1) ? (B1 + kg * N + colbase + b_q)
                          : (B2 + (kg - K1) * N + colbase + b_q);
        }
        pb = *reinterpret_cast<const float4*>(p);
    };

    fetchA(0);
    fetchB(0);

#pragma unroll 1
    for (int t = 0; t < T; ++t) {
        As[a_k0 + 0][a_row] = pa.x;
        As[a_k0 + 1][a_row] = pa.y;
        As[a_k0 + 2][a_row] = pa.z;
        As[a_k0 + 3][a_row] = pa.w;
        *reinterpret_cast<float4*>(&Bs[b_krow][b_q]) = pb;
        __syncthreads();

        if (t + 1 < T) { fetchA(t + 1); fetchB(t + 1); }

#pragma unroll
        for (int k = 0; k < 8; ++k) {
            float4 a0 = *reinterpret_cast<const float4*>(&As[k][ty * 8]);
            float4 a1 = *reinterpret_cast<const float4*>(&As[k][ty * 8 + 4]);
            float4 b0 = *reinterpret_cast<const float4*>(&Bs[k][tx * 8]);
            float4 b1 = *reinterpret_cast<const float4*>(&Bs[k][tx * 8 + 4]);
            float av[8] = {a0.x, a0.y, a0.z, a0.w, a1.x, a1.y, a1.z, a1.w};
            float bv[8] = {b0.x, b0.y, b0.z, b0.w, b1.x, b1.y, b1.z, b1.w};
#pragma unroll
            for (int i = 0; i < 8; ++i)
#pragma unroll
                for (int j = 0; j < 8; ++j)
                    acc[i][j] = fmaf(av[i], bv[j], acc[i][j]);
        }
        __syncthreads();
    }

    float bia[8];
#pragma unroll
    for (int j = 0; j < 8; ++j) bia[j] = bias[colbase + tx * 8 + j];

#pragma unroll
    for (int i = 0; i < 8; ++i) {
        int r = rowbase + ty * 8 + i;
        if (r < M) {
            float4 o0, o1;
            o0.x = fmaxf(acc[i][0] + bia[0], 0.f);
            o0.y = fmaxf(acc[i][1] + bia[1], 0.f);
            o0.z = fmaxf(acc[i][2] + bia[2], 0.f);
            o0.w = fmaxf(acc[i][3] + bia[3], 0.f);
            o1.x = fmaxf(acc[i][4] + bia[4], 0.f);
            o1.y = fmaxf(acc[i][5] + bia[5], 0.f);
            o1.z = fmaxf(acc[i][6] + bia[6], 0.f);
            o1.w = fmaxf(acc[i][7] + bia[7], 0.f);
            *reinterpret_cast<float4*>(&C[r * N + colbase + tx * 8])     = o0;
            *reinterpret_cast<float4*>(&C[r * N + colbase + tx * 8 + 4]) = o1;
        }
    }
}

// ---------------- per-graph online softmax denominator ----------------
// final[g,f] = max_nodes(exp(h-gmax)/zsum) = 1/zsum (exp monotone, gmax = max h)
__global__ void softmax_final_kernel()
{
    int g = blockIdx.x;
    int f = threadIdx.x;
    int s = g_start[g], e = g_start[g + 1];
    const float* __restrict__ h = g_h3;

    float mx0 = -FLT_MAX, mx1 = -FLT_MAX, mx2 = -FLT_MAX, mx3 = -FLT_MAX;
    float s0 = 0.f, s1 = 0.f, s2 = 0.f, s3 = 0.f;

    int i = s;
    for (; i + 4 <= e; i += 4) {
        float v0 = h[(i + 0) * HIDD + f];
        float v1 = h[(i + 1) * HIDD + f];
        float v2 = h[(i + 2) * HIDD + f];
        float v3 = h[(i + 3) * HIDD + f];
        if (v0 > mx0) { s0 *= __expf(mx0 - v0); mx0 = v0; }
        s0 += __expf(v0 - mx0);
        if (v1 > mx1) { s1 *= __expf(mx1 - v1); mx1 = v1; }
        s1 += __expf(v1 - mx1);
        if (v2 > mx2) { s2 *= __expf(mx2 - v2); mx2 = v2; }
        s2 += __expf(v2 - mx2);
        if (v3 > mx3) { s3 *= __expf(mx3 - v3); mx3 = v3; }
        s3 += __expf(v3 - mx3);
    }
    for (; i < e; ++i) {
        float v = h[i * HIDD + f];
        if (v > mx0) { s0 *= __expf(mx0 - v); mx0 = v; }
        s0 += __expf(v - mx0);
    }

    float Mx = fmaxf(fmaxf(mx0, mx1), fmaxf(mx2, mx3));
    float S  = s0 * __expf(mx0 - Mx) + s1 * __expf(mx1 - Mx)
             + s2 * __expf(mx2 - Mx) + s3 * __expf(mx3 - Mx);
    g_final[g * HIDD + f] = (e > s) ? (1.0f / S) : 0.f;
}

// ---------------- tiny readout: out = final @ Wr + br ----------------
__global__ void readout_kernel(const float* __restrict__ Wr, const float* __restrict__ br,
                               float* __restrict__ out, int ngr)
{
    int t = blockIdx.x * blockDim.x + threadIdx.x;
    if (t < ngr * 2) {
        int g = t >> 1, o = t & 1;
        float acc = br[o];
        const float* fr = &g_final[g * HIDD];
#pragma unroll 8
        for (int f = 0; f < HIDD; ++f) acc = fmaf(fr[f], Wr[f * 2 + o], acc);
        out[t] = acc;
    }
}

// ---------------- launch ----------------
extern "C" void kernel_launch(void* const* d_in, const int* in_sizes, int n_in,
                              void* d_out, int out_size)
{
    const float* x       = (const float*)d_in[0];
    const float* W_pool  = (const float*)d_in[1];
    const float* b_pool  = (const float*)d_in[2];
    const float* W_self  = (const float*)d_in[3];
    const float* W_neigh = (const float*)d_in[4];
    const float* b_sage  = (const float*)d_in[5];
    const float* W1      = (const float*)d_in[6];
    const float* b1      = (const float*)d_in[7];
    const float* W2      = (const float*)d_in[8];
    const float* b2      = (const float*)d_in[9];
    const float* Wr      = (const float*)d_in[10];
    const float* br      = (const float*)d_in[11];
    const int*   src     = (const int*)d_in[12];
    const int*   dst     = (const int*)d_in[13];
    const int*   gid     = (const int*)d_in[14];
    float*       out     = (float*)d_out;

    const int M = in_sizes[0] / IND;   // 100000
    const int E = in_sizes[12];        // 1600000
    const int G = out_size / 2;        // 256

    void *pm, *pn, *ph1, *ph2, *ph3;
    cudaGetSymbolAddress(&pm,  g_m);
    cudaGetSymbolAddress(&pn,  g_neigh);
    cudaGetSymbolAddress(&ph1, g_h1);
    cudaGetSymbolAddress(&ph2, g_h2);
    cudaGetSymbolAddress(&ph3, g_h3);

    const int nb1024 = (M + 1023) / 1024;

    // stage 0a: graph ranges (binary search over sorted gid)
    find_starts_kernel<<<1, 512>>>(gid, M, G);

    // stage 0b: CSR build (overlaps conceptually with stage 1 deps: none)
    zero_deg_kernel<<<(M + 255) / 256, 256>>>(M);
    hist_kernel<<<(E + 255) / 256, 256>>>(dst, E);
    block_sums_kernel<<<nb1024, 1024>>>(M);
    scan_bsum_kernel<<<1, 128>>>(nb1024, M, E);
    scan_block_kernel<<<nb1024, 1024>>>(M);
    scatter_kernel<<<(E + 255) / 256, 256>>>(src, dst, E);

    const int MB = (M + 127) / 128;

    // stage 1: m = relu(x @ W_pool + b_pool)
    gemm_bias_relu<128, 0, 128><<<dim3(MB, 1), 256>>>(
        x, nullptr, W_pool, nullptr, b_pool, (float*)pm, M);

    // stage 2: neigh[d] = max over in-edges of m[src]  (gather, no atomics)
    gather_max_kernel<<<(M * 32 + 255) / 256, 256>>>(M);

    // stage 3: h1 = relu(x @ W_self + neigh @ W_neigh + b_sage)   (fused K=256)
    gemm_bias_relu<128, 128, 256><<<dim3(MB, 2), 256>>>(
        x, (const float*)pn, W_self, W_neigh, b_sage, (float*)ph1, M);

    // stage 4/5: MLP
    gemm_bias_relu<256, 0, 256><<<dim3(MB, 2), 256>>>(
        (const float*)ph1, nullptr, W1, nullptr, b1, (float*)ph2, M);
    gemm_bias_relu<256, 0, 256><<<dim3(MB, 2), 256>>>(
        (const float*)ph2, nullptr, W2, nullptr, b2, (float*)ph3, M);

    // stage 6: per-graph softmax denominator -> final = 1/zsum
    softmax_final_kernel<<<G, HIDD>>>();

    // stage 7: out = final @ Wr + br
    readout_kernel<<<(G * 2 + 255) / 256, 256>>>(Wr, br, out, G);
}

// round 9
// speedup vs baseline: 2.8379x; 1.6409x over previous
#include <cuda_runtime.h>
#include <cuda_bf16.h>
#include <float.h>

#define NN   100000
#define NE   1600000
#define IND  128
#define HIDD 256
#define NG   256

// ---------------- static device scratch (allocation-free rule) ----------------
__device__ float g_m[NN * IND];        // relu(x @ W_pool + b_pool)
__device__ float g_neigh[NN * IND];    // segment_max over in-edges
__device__ float g_h1[NN * HIDD];
__device__ float g_h2[NN * HIDD];
__device__ float g_h3[NN * HIDD];
__device__ float g_final[NG * HIDD];   // 1/zsum per (graph, feature)
__device__ int   g_start[NG + 1];      // node range per graph (graph_id sorted)

// CSR scratch
__device__ int g_deg[NN];
__device__ int g_cursor[NN];
__device__ int g_off[NN + 1];
__device__ int g_esrc[NE];
__device__ int g_bsum[128];

// ---------------- graph ranges: gid sorted -> binary search ----------------
__global__ void find_starts_kernel(const int* __restrict__ gid, int n, int G) {
    int g = blockIdx.x * blockDim.x + threadIdx.x;
    if (g > G) return;
    int lo = 0, hi = n;
    while (lo < hi) {
        int mid = (lo + hi) >> 1;
        if (gid[mid] < g) lo = mid + 1; else hi = mid;
    }
    g_start[g] = lo;
}

// ---------------- CSR build ----------------
__global__ void zero_deg_kernel(int n) {
    int i = blockIdx.x * blockDim.x + threadIdx.x;
    if (i < n) g_deg[i] = 0;
}
__global__ void hist_kernel(const int* __restrict__ dst, int ne) {
    int e = blockIdx.x * blockDim.x + threadIdx.x;
    if (e < ne) atomicAdd(&g_deg[dst[e]], 1);
}
__global__ void block_sums_kernel(int n) {
    __shared__ int sh[1024];
    int i = blockIdx.x * 1024 + threadIdx.x;
    sh[threadIdx.x] = (i < n) ? g_deg[i] : 0;
    __syncthreads();
    for (int s = 512; s > 0; s >>= 1) {
        if (threadIdx.x < s) sh[threadIdx.x] += sh[threadIdx.x + s];
        __syncthreads();
    }
    if (threadIdx.x == 0) g_bsum[blockIdx.x] = sh[0];
}
__global__ void scan_bsum_kernel(int nb, int n, int ne) {
    __shared__ int sh[128];
    int t = threadIdx.x;
    sh[t] = (t < nb) ? g_bsum[t] : 0;
    __syncthreads();
    for (int d = 1; d < 128; d <<= 1) {
        int v = (t >= d) ? sh[t - d] : 0;
        __syncthreads();
        sh[t] += v;
        __syncthreads();
    }
    if (t < nb) g_bsum[t] = (t == 0) ? 0 : sh[t - 1];
    if (t == 0) g_off[n] = ne;
}
__global__ void scan_block_kernel(int n) {
    __shared__ int sh[1024];
    int t = threadIdx.x;
    int i = blockIdx.x * 1024 + t;
    int v = (i < n) ? g_deg[i] : 0;
    sh[t] = v;
    __syncthreads();
    for (int d = 1; d < 1024; d <<= 1) {
        int u = (t >= d) ? sh[t - d] : 0;
        __syncthreads();
        sh[t] += u;
        __syncthreads();
    }
    if (i < n) {
        int off = g_bsum[blockIdx.x] + sh[t] - v;
        g_off[i] = off;
        g_cursor[i] = off;
    }
}
__global__ void scatter_kernel(const int* __restrict__ src, const int* __restrict__ dst, int ne) {
    int e = blockIdx.x * blockDim.x + threadIdx.x;
    if (e < ne) {
        int pos = atomicAdd(&g_cursor[dst[e]], 1);
        g_esrc[pos] = src[e];
    }
}

// ---------------- gather max: warp per dst node, no atomics ----------------
__global__ void gather_max_kernel(int n) {
    int warp = (blockIdx.x * blockDim.x + threadIdx.x) >> 5;
    if (warp >= n) return;
    int lane = threadIdx.x & 31;
    int c = lane * 4;
    int beg = g_off[warp], end = g_off[warp + 1];
    float4 acc = make_float4(0.f, 0.f, 0.f, 0.f);
    int j = beg;
    for (; j + 2 <= end; j += 2) {
        int s0 = __ldg(&g_esrc[j]);
        int s1 = __ldg(&g_esrc[j + 1]);
        float4 v0 = *reinterpret_cast<const float4*>(&g_m[s0 * IND + c]);
        float4 v1 = *reinterpret_cast<const float4*>(&g_m[s1 * IND + c]);
        acc.x = fmaxf(acc.x, fmaxf(v0.x, v1.x));
        acc.y = fmaxf(acc.y, fmaxf(v0.y, v1.y));
        acc.z = fmaxf(acc.z, fmaxf(v0.z, v1.z));
        acc.w = fmaxf(acc.w, fmaxf(v0.w, v1.w));
    }
    if (j < end) {
        int s0 = __ldg(&g_esrc[j]);
        float4 v0 = *reinterpret_cast<const float4*>(&g_m[s0 * IND + c]);
        acc.x = fmaxf(acc.x, v0.x);
        acc.y = fmaxf(acc.y, v0.y);
        acc.z = fmaxf(acc.z, v0.z);
        acc.w = fmaxf(acc.w, v0.w);
    }
    *reinterpret_cast<float4*>(&g_neigh[warp * IND + c]) = acc;
}

// ---------------- bf16-split tensor-core GEMM + bias + relu -----------------
// C[M,N] = relu(A1[M,K1]@B1 + A2[M,K2]@B2 + bias), fp32 in/out.
// Split a = hi + lo (bf16 each); D += Ahi*Bhi + Ahi*Blo + Alo*Bhi (fp32 acc).
// Block 128x128, 8 warps (4m x 2n), warp tile 32x64, BK=32.
// As/Bs: [hi|lo][row][k], padded to 40 shorts (20 words) -> conflict-free frags.

__device__ __forceinline__ void cvt_hl(float x, unsigned short& h, unsigned short& l) {
    __nv_bfloat16 bh = __float2bfloat16(x);
    __nv_bfloat16 bl = __float2bfloat16(x - __bfloat162float(bh));
    h = __bfloat16_as_ushort(bh);
    l = __bfloat16_as_ushort(bl);
}

__device__ __forceinline__ void mma16816(float* d, const unsigned* a, const unsigned* b) {
    asm volatile("mma.sync.aligned.m16n8k16.row.col.f32.bf16.bf16.f32 "
                 "{%0,%1,%2,%3}, {%4,%5,%6,%7}, {%8,%9}, {%0,%1,%2,%3};"
                 : "+f"(d[0]), "+f"(d[1]), "+f"(d[2]), "+f"(d[3])
                 : "r"(a[0]), "r"(a[1]), "r"(a[2]), "r"(a[3]),
                   "r"(b[0]), "r"(b[1]));
}

template<int K1, int K2, int N>
__global__ __launch_bounds__(256, 2)
void gemm_tc(const float* __restrict__ A1, const float* __restrict__ A2,
             const float* __restrict__ B1, const float* __restrict__ B2,
             const float* __restrict__ bias, float* __restrict__ C, int M)
{
    constexpr int KT = K1 + K2;
    constexpr int T  = KT / 32;

    __shared__ unsigned short As[2][128][40];   // [hi/lo][row][k]
    __shared__ unsigned short Bs[2][128][40];   // [hi/lo][n][k]

    const int tid     = threadIdx.x;
    const int rowbase = blockIdx.x * 128;
    const int colbase = blockIdx.y * 128;

    const int lane = tid & 31;
    const int wid  = tid >> 5;
    const int wm   = (wid & 3) * 32;    // warp row base
    const int wn   = (wid >> 2) * 64;   // warp col base
    const int fr   = lane >> 2;         // fragment row / n
    const int fc   = (lane & 3) * 2;    // fragment k pair base

    // staging coords
    const int a_row = tid >> 1;
    const int a_k0  = (tid & 1) * 16;
    const int a_grow = rowbase + a_row;
    const bool a_ok  = a_grow < M;
    const int b_n   = tid & 127;
    const int b_kqb = tid >> 7;

    float acc[2][8][4];
#pragma unroll
    for (int mt = 0; mt < 2; ++mt)
#pragma unroll
        for (int nt = 0; nt < 8; ++nt)
#pragma unroll
            for (int q = 0; q < 4; ++q) acc[mt][nt][q] = 0.f;

#pragma unroll 1
    for (int t = 0; t < T; ++t) {
        const int kc = t * 32;
        __syncthreads();

        // ---- stage A (convert fp32 -> bf16 hi/lo) ----
        {
            const float* ap;
            if constexpr (K2 == 0) {
                ap = A1 + (size_t)a_grow * K1 + kc + a_k0;
            } else {
                ap = (kc < K1) ? A1 + (size_t)a_grow * K1 + kc + a_k0
                               : A2 + (size_t)a_grow * K2 + (kc - K1) + a_k0;
            }
#pragma unroll
            for (int i = 0; i < 4; ++i) {
                float4 v = a_ok ? *reinterpret_cast<const float4*>(ap + i * 4)
                                : make_float4(0.f, 0.f, 0.f, 0.f);
                unsigned short h[4], l[4];
                cvt_hl(v.x, h[0], l[0]); cvt_hl(v.y, h[1], l[1]);
                cvt_hl(v.z, h[2], l[2]); cvt_hl(v.w, h[3], l[3]);
                uint2 hw, lw;
                hw.x = ((unsigned)h[1] << 16) | h[0];
                hw.y = ((unsigned)h[3] << 16) | h[2];
                lw.x = ((unsigned)l[1] << 16) | l[0];
                lw.y = ((unsigned)l[3] << 16) | l[2];
                *reinterpret_cast<uint2*>(&As[0][a_row][a_k0 + i * 4]) = hw;
                *reinterpret_cast<uint2*>(&As[1][a_row][a_k0 + i * 4]) = lw;
            }
        }
        // ---- stage B transposed [n][k] (coalesced gmem, strided smem) ----
        {
#pragma unroll
            for (int it = 0; it < 4; ++it) {
                int kq = it * 2 + b_kqb;        // 0..7
                int kg = kc + kq * 4;
                const float* bp;
                if constexpr (K2 == 0) {
                    bp = B1 + (size_t)kg * N + colbase + b_n;
                } else {
                    bp = (kg < K1) ? B1 + (size_t)kg * N + colbase + b_n
                                   : B2 + (size_t)(kg - K1) * N + colbase + b_n;
                }
                unsigned short h[4], l[4];
#pragma unroll
                for (int i = 0; i < 4; ++i) cvt_hl(bp[(size_t)i * N], h[i], l[i]);
                uint2 hw, lw;
                hw.x = ((unsigned)h[1] << 16) | h[0];
                hw.y = ((unsigned)h[3] << 16) | h[2];
                lw.x = ((unsigned)l[1] << 16) | l[0];
                lw.y = ((unsigned)l[3] << 16) | l[2];
                *reinterpret_cast<uint2*>(&Bs[0][b_n][kq * 4]) = hw;
                *reinterpret_cast<uint2*>(&Bs[1][b_n][kq * 4]) = lw;
            }
        }
        __syncthreads();

        // ---- compute: two k16 steps ----
#pragma unroll
        for (int kk = 0; kk < 32; kk += 16) {
            unsigned ah[2][4], al[2][4];
#pragma unroll
            for (int mt = 0; mt < 2; ++mt) {
                int r0 = wm + mt * 16 + fr;
                ah[mt][0] = *reinterpret_cast<const unsigned*>(&As[0][r0    ][kk + fc    ]);
                ah[mt][1] = *reinterpret_cast<const unsigned*>(&As[0][r0 + 8][kk + fc    ]);
                ah[mt][2] = *reinterpret_cast<const unsigned*>(&As[0][r0    ][kk + fc + 8]);
                ah[mt][3] = *reinterpret_cast<const unsigned*>(&As[0][r0 + 8][kk + fc + 8]);
                al[mt][0] = *reinterpret_cast<const unsigned*>(&As[1][r0    ][kk + fc    ]);
                al[mt][1] = *reinterpret_cast<const unsigned*>(&As[1][r0 + 8][kk + fc    ]);
                al[mt][2] = *reinterpret_cast<const unsigned*>(&As[1][r0    ][kk + fc + 8]);
                al[mt][3] = *reinterpret_cast<const unsigned*>(&As[1][r0 + 8][kk + fc + 8]);
            }
#pragma unroll
            for (int nt = 0; nt < 8; ++nt) {
                int nb = wn + nt * 8 + fr;
                unsigned bh[2], bl[2];
                bh[0] = *reinterpret_cast<const unsigned*>(&Bs[0][nb][kk + fc    ]);
                bh[1] = *reinterpret_cast<const unsigned*>(&Bs[0][nb][kk + fc + 8]);
                bl[0] = *reinterpret_cast<const unsigned*>(&Bs[1][nb][kk + fc    ]);
                bl[1] = *reinterpret_cast<const unsigned*>(&Bs[1][nb][kk + fc + 8]);
#pragma unroll
                for (int mt = 0; mt < 2; ++mt) {
                    mma16816(acc[mt][nt], ah[mt], bh);   // hi*hi
                    mma16816(acc[mt][nt], ah[mt], bl);   // hi*lo
                    mma16816(acc[mt][nt], al[mt], bh);   // lo*hi
                }
            }
        }
    }

    // ---- epilogue: bias + relu ----
#pragma unroll
    for (int nt = 0; nt < 8; ++nt) {
        int cb = colbase + wn + nt * 8 + fc;
        float2 bi = *reinterpret_cast<const float2*>(&bias[cb]);
#pragma unroll
        for (int mt = 0; mt < 2; ++mt) {
            int r0 = rowbase + wm + mt * 16 + fr;
            if (r0 < M) {
                float2 o;
                o.x = fmaxf(acc[mt][nt][0] + bi.x, 0.f);
                o.y = fmaxf(acc[mt][nt][1] + bi.y, 0.f);
                *reinterpret_cast<float2*>(&C[(size_t)r0 * N + cb]) = o;
            }
            if (r0 + 8 < M) {
                float2 o;
                o.x = fmaxf(acc[mt][nt][2] + bi.x, 0.f);
                o.y = fmaxf(acc[mt][nt][3] + bi.y, 0.f);
                *reinterpret_cast<float2*>(&C[(size_t)(r0 + 8) * N + cb]) = o;
            }
        }
    }
}

// ---------------- per-graph online softmax denominator ----------------
__global__ void softmax_final_kernel()
{
    int g = blockIdx.x;
    int f = threadIdx.x;
    int s = g_start[g], e = g_start[g + 1];
    const float* __restrict__ h = g_h3;

    float mx0 = -FLT_MAX, mx1 = -FLT_MAX, mx2 = -FLT_MAX, mx3 = -FLT_MAX;
    float s0 = 0.f, s1 = 0.f, s2 = 0.f, s3 = 0.f;

    int i = s;
    for (; i + 4 <= e; i += 4) {
        float v0 = h[(i + 0) * HIDD + f];
        float v1 = h[(i + 1) * HIDD + f];
        float v2 = h[(i + 2) * HIDD + f];
        float v3 = h[(i + 3) * HIDD + f];
        if (v0 > mx0) { s0 *= __expf(mx0 - v0); mx0 = v0; }
        s0 += __expf(v0 - mx0);
        if (v1 > mx1) { s1 *= __expf(mx1 - v1); mx1 = v1; }
        s1 += __expf(v1 - mx1);
        if (v2 > mx2) { s2 *= __expf(mx2 - v2); mx2 = v2; }
        s2 += __expf(v2 - mx2);
        if (v3 > mx3) { s3 *= __expf(mx3 - v3); mx3 = v3; }
        s3 += __expf(v3 - mx3);
    }
    for (; i < e; ++i) {
        float v = h[i * HIDD + f];
        if (v > mx0) { s0 *= __expf(mx0 - v); mx0 = v; }
        s0 += __expf(v - mx0);
    }

    float Mx = fmaxf(fmaxf(mx0, mx1), fmaxf(mx2, mx3));
    float S  = s0 * __expf(mx0 - Mx) + s1 * __expf(mx1 - Mx)
             + s2 * __expf(mx2 - Mx) + s3 * __expf(mx3 - Mx);
    g_final[g * HIDD + f] = (e > s) ? (1.0f / S) : 0.f;
}

// ---------------- tiny readout: out = final @ Wr + br ----------------
__global__ void readout_kernel(const float* __restrict__ Wr, const float* __restrict__ br,
                               float* __restrict__ out, int ngr)
{
    int t = blockIdx.x * blockDim.x + threadIdx.x;
    if (t < ngr * 2) {
        int g = t >> 1, o = t & 1;
        float acc = br[o];
        const float* fr = &g_final[g * HIDD];
#pragma unroll 8
        for (int f = 0; f < HIDD; ++f) acc = fmaf(fr[f], Wr[f * 2 + o], acc);
        out[t] = acc;
    }
}

// ---------------- launch ----------------
extern "C" void kernel_launch(void* const* d_in, const int* in_sizes, int n_in,
                              void* d_out, int out_size)
{
    const float* x       = (const float*)d_in[0];
    const float* W_pool  = (const float*)d_in[1];
    const float* b_pool  = (const float*)d_in[2];
    const float* W_self  = (const float*)d_in[3];
    const float* W_neigh = (const float*)d_in[4];
    const float* b_sage  = (const float*)d_in[5];
    const float* W1      = (const float*)d_in[6];
    const float* b1      = (const float*)d_in[7];
    const float* W2      = (const float*)d_in[8];
    const float* b2      = (const float*)d_in[9];
    const float* Wr      = (const float*)d_in[10];
    const float* br      = (const float*)d_in[11];
    const int*   src     = (const int*)d_in[12];
    const int*   dst     = (const int*)d_in[13];
    const int*   gid     = (const int*)d_in[14];
    float*       out     = (float*)d_out;

    const int M = in_sizes[0] / IND;   // 100000
    const int E = in_sizes[12];        // 1600000
    const int G = out_size / 2;        // 256

    void *pm, *pn, *ph1, *ph2, *ph3;
    cudaGetSymbolAddress(&pm,  g_m);
    cudaGetSymbolAddress(&pn,  g_neigh);
    cudaGetSymbolAddress(&ph1, g_h1);
    cudaGetSymbolAddress(&ph2, g_h2);
    cudaGetSymbolAddress(&ph3, g_h3);

    const int nb1024 = (M + 1023) / 1024;

    // stage 0a: graph ranges
    find_starts_kernel<<<1, 512>>>(gid, M, G);

    // stage 0b: CSR build
    zero_deg_kernel<<<(M + 255) / 256, 256>>>(M);
    hist_kernel<<<(E + 255) / 256, 256>>>(dst, E);
    block_sums_kernel<<<nb1024, 1024>>>(M);
    scan_bsum_kernel<<<1, 128>>>(nb1024, M, E);
    scan_block_kernel<<<nb1024, 1024>>>(M);
    scatter_kernel<<<(E + 255) / 256, 256>>>(src, dst, E);

    const int MB = (M + 127) / 128;

    // stage 1: m = relu(x @ W_pool + b_pool)
    gemm_tc<128, 0, 128><<<dim3(MB, 1), 256>>>(
        x, nullptr, W_pool, nullptr, b_pool, (float*)pm, M);

    // stage 2: neigh[d] = max over in-edges of m[src]
    gather_max_kernel<<<(M * 32 + 255) / 256, 256>>>(M);

    // stage 3: h1 = relu(x @ W_self + neigh @ W_neigh + b_sage)
    gemm_tc<128, 128, 256><<<dim3(MB, 2), 256>>>(
        x, (const float*)pn, W_self, W_neigh, b_sage, (float*)ph1, M);

    // stage 4/5: MLP
    gemm_tc<256, 0, 256><<<dim3(MB, 2), 256>>>(
        (const float*)ph1, nullptr, W1, nullptr, b1, (float*)ph2, M);
    gemm_tc<256, 0, 256><<<dim3(MB, 2), 256>>>(
        (const float*)ph2, nullptr, W2, nullptr, b2, (float*)ph3, M);

    // stage 6: per-graph softmax denominator -> final = 1/zsum
    softmax_final_kernel<<<G, HIDD>>>();

    // stage 7: out = final @ Wr + br
    readout_kernel<<<(G * 2 + 255) / 256, 256>>>(Wr, br, out, G);
}